// round 1
// baseline (speedup 1.0000x reference)
#include <cuda_runtime.h>
#include <cuda_bf16.h>
#include <cstdint>

// Problem constants (fixed by the dataset)
#define BATCH   8192
#define SEQ     8
#define HID     2048
#define NEXP    64
#define TOPK    8
#define ROWSTR  (SEQ * HID)      // 16384 floats between consecutive b at s=0

// GEMM tiling
#define BM 128
#define BN 64
#define BK 16
#define SPLITS 4
#define KSPLIT (HID / SPLITS)    // 512
#define NSTAGE (KSPLIT / BK)     // 32

// Scratch (device globals — no allocation allowed)
__device__ float g_partial[SPLITS][BATCH * NEXP];  // 8 MB
__device__ float g_imp[NEXP];
__device__ int   g_cnt[NEXP];

// ---------------------------------------------------------------------------
// Kernel 1: zero the small accumulators (graph replays must start clean)
// ---------------------------------------------------------------------------
__global__ void init_kernel() {
    int t = threadIdx.x;
    if (t < NEXP) { g_imp[t] = 0.0f; g_cnt[t] = 0; }
}

// ---------------------------------------------------------------------------
// Kernel 2: logits GEMM. A = hidden_states[:,0,:] (row stride 16384),
// B = gate_w [64,2048] (transposed on the fly into smem [k][n]).
// f32x2 packed FMA accumulators, double-buffered smem, split-K=4.
// ---------------------------------------------------------------------------
__global__ void __launch_bounds__(128, 2)
gemm_kernel(const float* __restrict__ hs, const float* __restrict__ gw) {
    __shared__ __align__(16) float As[2][BK][BM];
    __shared__ __align__(16) float Bs[2][BK][BN];

    const int t  = threadIdx.x;          // 0..127
    const int m0 = blockIdx.x * BM;
    const int sp = blockIdx.y;
    const int k0 = sp * KSPLIT;

    const int ty   = t >> 3;             // 0..15
    const int tx   = t & 7;              // 0..7
    const int row0 = ty * 8;
    const int col0 = tx * 8;

    // A: thread t owns global row (m0+t); loads 16 floats (4x float4) per stage
    const float* aptr = hs + (size_t)(m0 + t) * ROWSTR + k0;
    // B: thread t loads expert bn, k-groups {bg, bg+2}
    const int bn = t & 63;
    const int bg = t >> 6;               // 0 or 1
    const float* bptr = gw + (size_t)bn * HID + k0;

    float4 ar[4];
    float4 br[2];

    // ---- prefetch stage 0 ----
#pragma unroll
    for (int kk = 0; kk < 4; kk++) ar[kk] = *(const float4*)(aptr + kk * 4);
    br[0] = *(const float4*)(bptr + bg * 4);
    br[1] = *(const float4*)(bptr + (bg + 2) * 4);

#pragma unroll
    for (int kk = 0; kk < 4; kk++) {
        As[0][kk * 4 + 0][t] = ar[kk].x;
        As[0][kk * 4 + 1][t] = ar[kk].y;
        As[0][kk * 4 + 2][t] = ar[kk].z;
        As[0][kk * 4 + 3][t] = ar[kk].w;
    }
    {
        Bs[0][bg * 4 + 0][bn] = br[0].x;
        Bs[0][bg * 4 + 1][bn] = br[0].y;
        Bs[0][bg * 4 + 2][bn] = br[0].z;
        Bs[0][bg * 4 + 3][bn] = br[0].w;
        int g2 = bg + 2;
        Bs[0][g2 * 4 + 0][bn] = br[1].x;
        Bs[0][g2 * 4 + 1][bn] = br[1].y;
        Bs[0][g2 * 4 + 2][bn] = br[1].z;
        Bs[0][g2 * 4 + 3][bn] = br[1].w;
    }
    __syncthreads();

    unsigned long long acc[8][4];
#pragma unroll
    for (int i = 0; i < 8; i++)
#pragma unroll
        for (int j = 0; j < 4; j++) acc[i][j] = 0ULL;

    for (int s = 0; s < NSTAGE; s++) {
        const int cur = s & 1;

        // issue next-stage global loads early (hidden behind compute)
        if (s + 1 < NSTAGE) {
            const float* ap = aptr + (size_t)(s + 1) * BK;
#pragma unroll
            for (int kk = 0; kk < 4; kk++) ar[kk] = *(const float4*)(ap + kk * 4);
            const float* bp = bptr + (size_t)(s + 1) * BK;
            br[0] = *(const float4*)(bp + bg * 4);
            br[1] = *(const float4*)(bp + (bg + 2) * 4);
        }

        // compute current stage
#pragma unroll
        for (int k = 0; k < BK; k++) {
            float4 a0 = *(const float4*)&As[cur][k][row0];
            float4 a1 = *(const float4*)&As[cur][k][row0 + 4];
            ulonglong2 b0 = *(const ulonglong2*)&Bs[cur][k][col0];
            ulonglong2 b1 = *(const ulonglong2*)&Bs[cur][k][col0 + 4];

            float av[8] = {a0.x, a0.y, a0.z, a0.w, a1.x, a1.y, a1.z, a1.w};
            unsigned long long bv[4] = {b0.x, b0.y, b1.x, b1.y};

#pragma unroll
            for (int i = 0; i < 8; i++) {
                unsigned long long a2;
                asm("mov.b64 %0, {%1, %1};" : "=l"(a2) : "f"(av[i]));
#pragma unroll
                for (int j = 0; j < 4; j++) {
                    asm("fma.rn.f32x2 %0, %1, %2, %0;"
                        : "+l"(acc[i][j]) : "l"(a2), "l"(bv[j]));
                }
            }
        }

        // store next stage into the other buffer
        if (s + 1 < NSTAGE) {
            const int nxt = cur ^ 1;
#pragma unroll
            for (int kk = 0; kk < 4; kk++) {
                As[nxt][kk * 4 + 0][t] = ar[kk].x;
                As[nxt][kk * 4 + 1][t] = ar[kk].y;
                As[nxt][kk * 4 + 2][t] = ar[kk].z;
                As[nxt][kk * 4 + 3][t] = ar[kk].w;
            }
            Bs[nxt][bg * 4 + 0][bn] = br[0].x;
            Bs[nxt][bg * 4 + 1][bn] = br[0].y;
            Bs[nxt][bg * 4 + 2][bn] = br[0].z;
            Bs[nxt][bg * 4 + 3][bn] = br[0].w;
            int g2 = bg + 2;
            Bs[nxt][g2 * 4 + 0][bn] = br[1].x;
            Bs[nxt][g2 * 4 + 1][bn] = br[1].y;
            Bs[nxt][g2 * 4 + 2][bn] = br[1].z;
            Bs[nxt][g2 * 4 + 3][bn] = br[1].w;
            __syncthreads();
        }
    }

    // epilogue: 64-bit stores of packed pairs
#pragma unroll
    for (int i = 0; i < 8; i++) {
        float* op = &g_partial[sp][(size_t)(m0 + row0 + i) * NEXP + col0];
#pragma unroll
        for (int j = 0; j < 4; j++) {
            ((unsigned long long*)op)[j] = acc[i][j];
        }
    }
}

// ---------------------------------------------------------------------------
// Kernel 3: warp-per-row softmax + top-8 + weights + importance/load counts.
// Lane l owns experts l and l+32. Output layout:
//   out[0 .. B*8)          topk_idx (as float)
//   out[B*8 .. 2*B*8)      topk_weights
//   out[2*B*8]             aux_loss (written by finalize)
// ---------------------------------------------------------------------------
__global__ void __launch_bounds__(256)
router_kernel(float* __restrict__ out) {
    __shared__ float s_imp[NEXP];
    __shared__ int   s_cnt[NEXP];
    const int tid = threadIdx.x;
    if (tid < NEXP) { s_imp[tid] = 0.0f; s_cnt[tid] = 0; }
    __syncthreads();

    const int lane = tid & 31;
    const int row  = (blockIdx.x * blockDim.x + tid) >> 5;  // grid sized exactly

    // sum split-K partials
    float l0 = 0.0f, l1 = 0.0f;
#pragma unroll
    for (int sp = 0; sp < SPLITS; sp++) {
        const float* p = &g_partial[sp][(size_t)row * NEXP];
        l0 += p[lane];
        l1 += p[lane + 32];
    }

    // softmax over 64
    float m = fmaxf(l0, l1);
#pragma unroll
    for (int off = 16; off; off >>= 1)
        m = fmaxf(m, __shfl_xor_sync(0xffffffffu, m, off));
    float p0 = __expf(l0 - m);
    float p1 = __expf(l1 - m);
    float sm = p0 + p1;
#pragma unroll
    for (int off = 16; off; off >>= 1)
        sm += __shfl_xor_sync(0xffffffffu, sm, off);
    float inv = 1.0f / sm;
    p0 *= inv;
    p1 *= inv;

    // importance accumulation (block-staged)
    atomicAdd(&s_imp[lane], p0);
    atomicAdd(&s_imp[lane + 32], p1);

    // top-8 via iterated warp argmax (tie -> smaller index, matches lax.top_k)
    bool sel0 = false, sel1 = false;
    float wsum = 0.0f, myv = 0.0f;
    int myi = 0;
#pragma unroll
    for (int it = 0; it < TOPK; it++) {
        float cv = sel0 ? -1.0f : p0;   // probs are > 0
        int   ci = lane;
        if (!sel1 && p1 > cv) { cv = p1; ci = lane + 32; }
#pragma unroll
        for (int off = 16; off; off >>= 1) {
            float ov = __shfl_xor_sync(0xffffffffu, cv, off);
            int   oi = __shfl_xor_sync(0xffffffffu, ci, off);
            if (ov > cv || (ov == cv && oi < ci)) { cv = ov; ci = oi; }
        }
        wsum += cv;
        if (ci == lane)           sel0 = true;
        else if (ci == lane + 32) sel1 = true;
        if (lane == it) { myv = cv; myi = ci; }
        if (lane == 0)  atomicAdd(&s_cnt[ci], 1);
    }

    float invw = 1.0f / fmaxf(wsum, 1e-8f);
    if (lane < TOPK) {
        out[(size_t)row * TOPK + lane] = (float)myi;
        out[(size_t)BATCH * TOPK + (size_t)row * TOPK + lane] = myv * invw;
    }

    __syncthreads();
    if (tid < NEXP) {
        atomicAdd(&g_imp[tid], s_imp[tid]);
        atomicAdd(&g_cnt[tid], s_cnt[tid]);
    }
}

// ---------------------------------------------------------------------------
// Kernel 4: aux loss = sum_e E * (imp_e/B) * (cnt_e/(B*K))
// ---------------------------------------------------------------------------
__global__ void finalize_kernel(float* __restrict__ out) {
    __shared__ float red[NEXP];
    int t = threadIdx.x;
    float v = (float)NEXP * (g_imp[t] / (float)BATCH) *
              ((float)g_cnt[t] / (float)(BATCH * TOPK));
    red[t] = v;
    __syncthreads();
    if (t == 0) {
        float s = 0.0f;
#pragma unroll
        for (int i = 0; i < NEXP; i++) s += red[i];
        out[(size_t)2 * BATCH * TOPK] = s;
    }
}

// ---------------------------------------------------------------------------
extern "C" void kernel_launch(void* const* d_in, const int* in_sizes, int n_in,
                              void* d_out, int out_size) {
    const float* hs  = (const float*)d_in[0];   // [8192, 8, 2048] f32
    const float* gw  = (const float*)d_in[1];   // [64, 2048] f32
    float*       out = (float*)d_out;           // 131073 f32

    init_kernel<<<1, 64>>>();
    gemm_kernel<<<dim3(BATCH / BM, SPLITS), 128>>>(hs, gw);
    router_kernel<<<(BATCH * 32) / 256, 256>>>(out);
    finalize_kernel<<<1, 64>>>(out);
}